// round 10
// baseline (speedup 1.0000x reference)
#include <cuda_runtime.h>
#include <stdint.h>
#include <math.h>

// ---------------- problem constants ----------------
constexpr int WID    = 512;
constexpr int SEQL   = 1752;
constexpr int BLK    = 146;   // 128 frame + delim + 16 dyn + delim
constexpr int NFR    = 12;    // N frames (13-1)
constexpr int NB     = 4;     // batch
constexpr int NH     = 8;     // heads
constexpr int NLAYER = 6;
constexpr int MROWS  = NB * SEQL;        // 7008
constexpr int MPAD   = 7040;             // padded to /128
constexpr int MHEAD  = NB * NFR * 128;   // 6144 logit rows
constexpr int GEMM_GRID_CAP = 296;       // 148 SMs x 2 CTAs

// ---------------- scratch (device globals; no cudaMalloc allowed) ----------------
__device__ float g_h  [(size_t)MPAD * WID];
__device__ float g_a  [(size_t)MPAD * WID];
__device__ float g_qkv[(size_t)MPAD * 3 * WID];
__device__ float g_o  [(size_t)MPAD * WID];
__device__ float g_mlp[(size_t)MPAD * 4 * WID];
__device__ float g_hf [(size_t)MHEAD * WID];
// tf32-pre-rounded weights: qkv | out | fc | proj | head
constexpr size_t W_QKV  = 0;
constexpr size_t W_OUT  = W_QKV + (size_t)NLAYER * 1536 * 512;
constexpr size_t W_FC   = W_OUT + (size_t)NLAYER * 512 * 512;
constexpr size_t W_PROJ = W_FC  + (size_t)NLAYER * 2048 * 512;
constexpr size_t W_HEAD = W_PROJ + (size_t)NLAYER * 512 * 2048;
constexpr size_t W_TOT  = W_HEAD + (size_t)1024 * 512;
__device__ float g_w[W_TOT];

// ---------------- helpers ----------------
__device__ __forceinline__ float ftf32(float x) {
  unsigned int u = __float_as_uint(x), r;
  asm("cvt.rna.tf32.f32 %0, %1;" : "=r"(r) : "r"(u));
  return __uint_as_float(r);
}

__device__ __forceinline__ void mma_tf32(float* d, const float* a, const float* b) {
  asm volatile(
      "mma.sync.aligned.m16n8k8.row.col.f32.tf32.tf32.f32 "
      "{%0,%1,%2,%3}, {%4,%5,%6,%7}, {%8,%9}, {%0,%1,%2,%3};"
      : "+f"(d[0]), "+f"(d[1]), "+f"(d[2]), "+f"(d[3])
      : "r"(__float_as_uint(a[0])), "r"(__float_as_uint(a[1])),
        "r"(__float_as_uint(a[2])), "r"(__float_as_uint(a[3])),
        "r"(__float_as_uint(b[0])), "r"(__float_as_uint(b[1])));
}

__device__ __forceinline__ void cp_async16(void* smem_dst, const void* gsrc) {
  unsigned int sa = (unsigned int)__cvta_generic_to_shared(smem_dst);
  asm volatile("cp.async.ca.shared.global [%0], [%1], 16;" :: "r"(sa), "l"(gsrc));
}

// ---------------- weight pre-rounding ----------------
__global__ void round_w_kernel(const float* __restrict__ src, float* __restrict__ dst, int n4) {
  int i = blockIdx.x * 256 + threadIdx.x;
  if (i >= n4) return;
  float4 v = ((const float4*)src)[i];
  v.x = ftf32(v.x); v.y = ftf32(v.y); v.z = ftf32(v.z); v.w = ftf32(v.w);
  ((float4*)dst)[i] = v;
}

// ---------------- build h = concat(x, delim, f, delim) + pos_emb ----------------
__global__ void build_h_kernel(const float* __restrict__ x, const float* __restrict__ f,
                               const float* __restrict__ delim) {
  __shared__ float rden[256];
  int tid = threadIdx.x;
  rden[tid] = (float)(1.0 / pow(10000.0, (double)tid / 256.0));
  __syncthreads();
  int row = blockIdx.x;
  float* hr = g_h + (size_t)row * WID;
  if (row >= MROWS) { hr[tid] = 0.f; hr[tid + 256] = 0.f; return; }
  int b = row / SEQL, s = row % SEQL;
  int fi = s / BLK, r = s - fi * BLK;
  const float* src;
  if (r < 128)                    src = x + (size_t)((b * NFR + fi) * 128 + r) * WID;
  else if (r == 128 || r == 145)  src = delim;
  else                            src = f + (size_t)(b * NFR * 16 + fi * 16 + (r - 129)) * WID;
#pragma unroll
  for (int c = tid; c < WID; c += 256) {
    float ang = (float)s * rden[c >> 1];
    float p = (c & 1) ? cosf(ang) : sinf(ang);
    hr[c] = src[c] + p;
  }
}

// ---------------- LayerNorm: one block per row; output pre-rounded to tf32 ----------------
__global__ void ln_kernel(const float* __restrict__ X, const float* __restrict__ sc,
                          const float* __restrict__ bi, float* __restrict__ Y) {
  int row = blockIdx.x;
  const float* xr = X + (size_t)row * WID;
  int tid = threadIdx.x;
  float v0 = xr[tid], v1 = xr[tid + 256];
  float s = v0 + v1, q = v0 * v0 + v1 * v1;
#pragma unroll
  for (int o = 16; o; o >>= 1) {
    s += __shfl_xor_sync(0xffffffffu, s, o);
    q += __shfl_xor_sync(0xffffffffu, q, o);
  }
  __shared__ float ss[8], sq[8];
  if ((tid & 31) == 0) { ss[tid >> 5] = s; sq[tid >> 5] = q; }
  __syncthreads();
  float ts = 0.f, tq = 0.f;
#pragma unroll
  for (int k = 0; k < 8; k++) { ts += ss[k]; tq += sq[k]; }
  float mu = ts * (1.f / WID);
  float var = tq * (1.f / WID) - mu * mu;
  float rstd = rsqrtf(var + 1e-5f);
  float* yr = Y + (size_t)row * WID;
  yr[tid]       = ftf32((v0 - mu) * rstd * sc[tid]       + bi[tid]);
  yr[tid + 256] = ftf32((v1 - mu) * rstd * sc[tid + 256] + bi[tid + 256]);
}

// ---------------- tf32 tensor-core GEMM (NT), persistent tiles ----------------
// Inputs pre-rounded to tf32. 128x128 tile, 8 warps (2m x 4n), warp 64x32.
// 4-stage cp.async pipeline; one commit_group EVERY iteration (empty if no load)
// so wait_group 2 provably makes stage i resident.
// EPI: 0 none, 1 +bias, 2 +bias->gelu(round), 3 +bias+residual
template <int EPI>
__global__ __launch_bounds__(256, 2) void gemm_tc(
    const float* __restrict__ A, const float* __restrict__ Bw,
    const float* __restrict__ bias, const float* __restrict__ Res,
    float* __restrict__ C, int N, int K, int nBN, int nTiles) {
  __shared__ __align__(16) float As[4][128][20];
  __shared__ __align__(16) float Bs[4][128][20];
  const int tid = threadIdx.x;
  const int lane = tid & 31, wid = tid >> 5;
  const int wm = wid & 1, wn = wid >> 1;
  const int l4 = lane & 3, l28 = lane >> 2;
  const int r0 = tid >> 2;
  const int seg = (tid & 3) << 2;
  const int nT = K >> 4;

  for (int tile = blockIdx.x; tile < nTiles; tile += gridDim.x) {
    const int bm = (tile / nBN) * 128;
    const int bn = (tile % nBN) * 128;
    const float* Ag = A + (size_t)(bm + r0) * K + seg;
    const float* Bg = Bw + (size_t)(bn + r0) * K + seg;

    float acc[4][4][4];
#pragma unroll
    for (int i = 0; i < 4; i++)
#pragma unroll
      for (int j = 0; j < 4; j++)
#pragma unroll
        for (int r = 0; r < 4; r++) acc[i][j][r] = 0.f;

    auto issue = [&](int s) {
      const int buf = s & 3;
      const int ko = s << 4;
      cp_async16(&As[buf][r0][seg],      Ag + ko);
      cp_async16(&As[buf][r0 + 64][seg], Ag + (size_t)64 * K + ko);
      cp_async16(&Bs[buf][r0][seg],      Bg + ko);
      cp_async16(&Bs[buf][r0 + 64][seg], Bg + (size_t)64 * K + ko);
      asm volatile("cp.async.commit_group;");
    };

    issue(0); issue(1); issue(2);

    for (int it = 0; it < nT; it++) {
      asm volatile("cp.async.wait_group 2;");  // stage it guaranteed resident
      __syncthreads();
      if (it + 3 < nT) issue(it + 3);
      else asm volatile("cp.async.commit_group;");  // keep group count in lockstep
      const float (*Asb)[20] = As[it & 3];
      const float (*Bsb)[20] = Bs[it & 3];
#pragma unroll
      for (int ks = 0; ks < 16; ks += 8) {
        float af[4][4], bf[4][2];
#pragma unroll
        for (int mi = 0; mi < 4; mi++) {
          int am = wm * 64 + mi * 16 + l28;
          af[mi][0] = Asb[am][ks + l4];
          af[mi][1] = Asb[am + 8][ks + l4];
          af[mi][2] = Asb[am][ks + 4 + l4];
          af[mi][3] = Asb[am + 8][ks + 4 + l4];
        }
#pragma unroll
        for (int nj = 0; nj < 4; nj++) {
          int cn = wn * 32 + nj * 8 + l28;
          bf[nj][0] = Bsb[cn][ks + l4];
          bf[nj][1] = Bsb[cn][ks + 4 + l4];
        }
#pragma unroll
        for (int mi = 0; mi < 4; mi++)
#pragma unroll
          for (int nj = 0; nj < 4; nj++) mma_tf32(acc[mi][nj], af[mi], bf[nj]);
      }
    }

    // epilogue
#pragma unroll
    for (int mi = 0; mi < 4; mi++) {
      int row0 = bm + wm * 64 + mi * 16 + l28;
#pragma unroll
      for (int half = 0; half < 2; half++) {
        int row = row0 + half * 8;
        float* crow = C + (size_t)row * N + bn + wn * 32;
        const float* rrow = (EPI == 3) ? (Res + (size_t)row * N + bn + wn * 32) : nullptr;
#pragma unroll
        for (int nj = 0; nj < 4; nj++) {
          int col = nj * 8 + 2 * l4;
          float v0 = acc[mi][nj][half * 2 + 0];
          float v1 = acc[mi][nj][half * 2 + 1];
          if (EPI >= 1) {
            v0 += bias[bn + wn * 32 + col];
            v1 += bias[bn + wn * 32 + col + 1];
          }
          if (EPI == 2) {
            v0 = ftf32(0.5f * v0 * (1.f + erff(v0 * 0.70710678118654752f)));
            v1 = ftf32(0.5f * v1 * (1.f + erff(v1 * 0.70710678118654752f)));
          }
          if (EPI == 3) { v0 += rrow[col]; v1 += rrow[col + 1]; }
          *(float2*)(crow + col) = make_float2(v0, v1);
        }
      }
    }
    __syncthreads();  // all reads of stage buffers done before next tile's issues
  }
}

// ---------------- structured attention, 64-key chunks, register softmax ----------------
// Thread map: tx = tid&15 (4 k-cols in scores / 4 d-cols in PV), ty = tid>>4 (4 q-rows).
// Warp = one ty-pair; each q-row's 16 k-owners are a half-warp -> shfl reductions.
__global__ __launch_bounds__(256) void attn_kernel(const float* __restrict__ qkv,
                                                   float* __restrict__ O) {
  const int fi = blockIdx.x >> 1, qt = blockIdx.x & 1;
  const int h = blockIdx.y, b = blockIdx.z;
  const int fs = fi * BLK;
  const int q0 = fs + qt * 64;
  const int nE = (fi > 0) ? (1 + 17 * (fi + 1)) : 17;
  const int nK = 128 + nE;
  const float* base = qkv + (size_t)b * SEQL * 1536;

  __shared__ __align__(16) float Qs[64][68];  // [d][q], pre-scaled
  __shared__ __align__(16) float Ks[64][68];  // [d][k], k xor-swizzled by (d>>4)<<2
  __shared__ __align__(16) float Vs[64][68];  // [k][d]
  __shared__ __align__(16) float Ps[64][68];  // [q][k]

  const int tid = threadIdx.x;
  {  // load Q tile (64 q x 64 d), scaled by 0.125
    int qr = tid >> 2;
    int c4 = tid & 3;
    const float* qrow = base + (size_t)(q0 + qr) * 1536 + h * 64;
#pragma unroll
    for (int j = 0; j < 4; j++) {
      int d = c4 * 16 + j * 4;
      float4 v = *(const float4*)(qrow + d);
      Qs[d + 0][qr] = v.x * 0.125f; Qs[d + 1][qr] = v.y * 0.125f;
      Qs[d + 2][qr] = v.z * 0.125f; Qs[d + 3][qr] = v.w * 0.125f;
    }
  }

  const int tx = tid & 15, ty = tid >> 4;
  float Oa[4][4];
  float m_run[4], l_run[4];
#pragma unroll
  for (int i = 0; i < 4; i++) {
    m_run[i] = -1e30f; l_run[i] = 0.f;
#pragma unroll
    for (int j = 0; j < 4; j++) Oa[i][j] = 0.f;
  }

  const int nCh = (nK + 63) / 64;
  for (int ch = 0; ch < nCh; ch++) {
    const int kb = ch * 64;
    __syncthreads();  // Q visible (1st) / Ks,Vs,Ps consumed (later)
    {  // load 64 gathered K,V rows
      int kr = tid >> 2;
      int c4 = tid & 3;
      int t = kb + kr;
      int pos;
      if (t >= nK) pos = fs;
      else if (t < 128) pos = fs + t;
      else {
        int e = t - 128;
        if (fi > 0) {
          if (e == 0) pos = fs - 1;
          else { int e2 = e - 1; pos = (e2 / 17) * BLK + 128 + (e2 % 17); }
        } else pos = 128 + e;
      }
      const float* krow = base + (size_t)pos * 1536 + 512 + h * 64;
      const float* vrow = base + (size_t)pos * 1536 + 1024 + h * 64;
      const int kc = kr ^ (c4 << 2);  // swizzle breaks 4-way store conflict
#pragma unroll
      for (int j = 0; j < 4; j++) {
        int d = c4 * 16 + j * 4;
        float4 kv = *(const float4*)(krow + d);
        Ks[d + 0][kc] = kv.x; Ks[d + 1][kc] = kv.y;
        Ks[d + 2][kc] = kv.z; Ks[d + 3][kc] = kv.w;
        float4 vv = *(const float4*)(vrow + d);
        *(float4*)(&Vs[kr][d]) = vv;
      }
    }
    __syncthreads();

    // scores: s[i][j] = q(ty*4+i) . k(kb + tx*4+j)
    float s[4][4];
#pragma unroll
    for (int i = 0; i < 4; i++)
#pragma unroll
      for (int j = 0; j < 4; j++) s[i][j] = 0.f;
#pragma unroll
    for (int d = 0; d < 64; d++) {
      float4 qv = *(const float4*)(&Qs[d][ty * 4]);
      float4 kv = *(const float4*)(&Ks[d][(tx * 4) ^ ((d >> 4) << 2)]);
      float qa[4] = {qv.x, qv.y, qv.z, qv.w};
      float ka[4] = {kv.x, kv.y, kv.z, kv.w};
#pragma unroll
      for (int i = 0; i < 4; i++)
#pragma unroll
        for (int j = 0; j < 4; j++) s[i][j] = fmaf(qa[i], ka[j], s[i][j]);
    }
    // mask tail
#pragma unroll
    for (int j = 0; j < 4; j++)
      if (kb + tx * 4 + j >= nK)
#pragma unroll
        for (int i = 0; i < 4; i++) s[i][j] = -1e30f;

    // register softmax per q-row (reduce across the 16-lane tx group)
#pragma unroll
    for (int i = 0; i < 4; i++) {
      float mx = fmaxf(fmaxf(s[i][0], s[i][1]), fmaxf(s[i][2], s[i][3]));
#pragma unroll
      for (int o = 1; o < 16; o <<= 1) mx = fmaxf(mx, __shfl_xor_sync(0xffffffffu, mx, o));
      float mn = fmaxf(m_run[i], mx);
      float al = expf(m_run[i] - mn);
      float ls = 0.f;
#pragma unroll
      for (int j = 0; j < 4; j++) {
        float p = expf(s[i][j] - mn);
        s[i][j] = p;
        ls += p;
      }
#pragma unroll
      for (int o = 1; o < 16; o <<= 1) ls += __shfl_xor_sync(0xffffffffu, ls, o);
      m_run[i] = mn;
      l_run[i] = l_run[i] * al + ls;
#pragma unroll
      for (int j = 0; j < 4; j++) Oa[i][j] *= al;
    }
    // write probabilities [q][k] (float4; each q-row fully owned by this warp)
#pragma unroll
    for (int i = 0; i < 4; i++)
      *(float4*)(&Ps[ty * 4 + i][tx * 4]) = make_float4(s[i][0], s[i][1], s[i][2], s[i][3]);
    __syncwarp();

    // PV: Oa[i][j] += sum_k P[q][k] * V[k][tx*4+j]
#pragma unroll
    for (int kq = 0; kq < 16; kq++) {
      float4 vr[4];
#pragma unroll
      for (int t2 = 0; t2 < 4; t2++) vr[t2] = *(const float4*)(&Vs[kq * 4 + t2][tx * 4]);
#pragma unroll
      for (int i = 0; i < 4; i++) {
        float4 pr = *(const float4*)(&Ps[ty * 4 + i][kq * 4]);  // broadcast within warp
        Oa[i][0] = fmaf(pr.x, vr[0].x, fmaf(pr.y, vr[1].x, fmaf(pr.z, vr[2].x, fmaf(pr.w, vr[3].x, Oa[i][0]))));
        Oa[i][1] = fmaf(pr.x, vr[0].y, fmaf(pr.y, vr[1].y, fmaf(pr.z, vr[2].y, fmaf(pr.w, vr[3].y, Oa[i][1]))));
        Oa[i][2] = fmaf(pr.x, vr[0].z, fmaf(pr.y, vr[1].z, fmaf(pr.z, vr[2].z, fmaf(pr.w, vr[3].z, Oa[i][2]))));
        Oa[i][3] = fmaf(pr.x, vr[0].w, fmaf(pr.y, vr[1].w, fmaf(pr.z, vr[2].w, fmaf(pr.w, vr[3].w, Oa[i][3]))));
      }
    }
  }

  // write out (pre-rounded to tf32 for out-proj GEMM)
#pragma unroll
  for (int i = 0; i < 4; i++) {
    int q = ty * 4 + i;
    float inv = 1.f / l_run[i];
    float* orow = O + (size_t)(b * SEQL + q0 + q) * WID + h * 64 + tx * 4;
    float4 ov = make_float4(ftf32(Oa[i][0] * inv), ftf32(Oa[i][1] * inv),
                            ftf32(Oa[i][2] * inv), ftf32(Oa[i][3] * inv));
    *(float4*)orow = ov;
  }
}

// ---------------- non-frame rows: attention output == V (pre-rounded) ----------------
__global__ void copyv_kernel() {
  int idx = blockIdx.x * 256 + threadIdx.x;
  if (idx >= NB * NFR * 18 * WID) return;
  int c = idx & 511;
  int rid = idx >> 9;
  int b = rid / (NFR * 18);
  int rr = rid % (NFR * 18);
  int fi = rr / 18, r = 128 + rr % 18;
  size_t srow = (size_t)b * SEQL + fi * BLK + r;
  g_o[srow * WID + c] = ftf32(g_qkv[srow * 1536 + 1024 + c]);
}

// ---------------- gather frame-token rows for the prediction head (pre-rounded) ----------------
__global__ void gather_kernel() {
  int idx = blockIdx.x * 256 + threadIdx.x;
  if (idx >= MHEAD * WID) return;
  int c = idx & 511, rid = idx >> 9;
  int b = rid / 1536, m = rid % 1536;
  int s = (m >> 7) * BLK + (m & 127);
  g_hf[(size_t)rid * WID + c] = ftf32(g_h[(size_t)(b * SEQL + s) * WID + c]);
}

// ---------------- launch ----------------
static inline int mini(int a, int b) { return a < b ? a : b; }

extern "C" void kernel_launch(void* const* d_in, const int* in_sizes, int n_in,
                              void* d_out, int out_size) {
  const float* x     = (const float*)d_in[0];
  const float* f     = (const float*)d_in[1];
  const float* delim = (const float*)d_in[2];
  const float* ln1s  = (const float*)d_in[3];
  const float* ln1b  = (const float*)d_in[4];
  const float* wqkv  = (const float*)d_in[5];
  const float* bqkv  = (const float*)d_in[6];
  const float* wout  = (const float*)d_in[7];
  const float* bout  = (const float*)d_in[8];
  const float* ln2s  = (const float*)d_in[9];
  const float* ln2b  = (const float*)d_in[10];
  const float* wfc   = (const float*)d_in[11];
  const float* bfc   = (const float*)d_in[12];
  const float* wproj = (const float*)d_in[13];
  const float* bproj = (const float*)d_in[14];
  const float* whead = (const float*)d_in[15];
  float* out = (float*)d_out;

  float *h, *a, *qkv, *o, *mlp, *hf, *w;
  cudaGetSymbolAddress((void**)&h, g_h);
  cudaGetSymbolAddress((void**)&a, g_a);
  cudaGetSymbolAddress((void**)&qkv, g_qkv);
  cudaGetSymbolAddress((void**)&o, g_o);
  cudaGetSymbolAddress((void**)&mlp, g_mlp);
  cudaGetSymbolAddress((void**)&hf, g_hf);
  cudaGetSymbolAddress((void**)&w, g_w);

  // pre-round all weights to tf32 (bit-exact with per-load cvt)
  {
    int n;
    n = NLAYER * 1536 * 512 / 4;
    round_w_kernel<<<(n + 255) / 256, 256>>>(wqkv, w + W_QKV, n);
    n = NLAYER * 512 * 512 / 4;
    round_w_kernel<<<(n + 255) / 256, 256>>>(wout, w + W_OUT, n);
    n = NLAYER * 2048 * 512 / 4;
    round_w_kernel<<<(n + 255) / 256, 256>>>(wfc, w + W_FC, n);
    n = NLAYER * 512 * 2048 / 4;
    round_w_kernel<<<(n + 255) / 256, 256>>>(wproj, w + W_PROJ, n);
    n = 1024 * 512 / 4;
    round_w_kernel<<<(n + 255) / 256, 256>>>(whead, w + W_HEAD, n);
  }

  build_h_kernel<<<MPAD, 256>>>(x, f, delim);

  const int MT = MPAD / 128;   // 55
  const int HT = MHEAD / 128;  // 48

  for (int l = 0; l < NLAYER; l++) {
    ln_kernel<<<MROWS, 256>>>(h, ln1s + l * WID, ln1b + l * WID, a);
    { int nbn = 1536 / 128, nt = MT * nbn;
      gemm_tc<1><<<mini(nt, GEMM_GRID_CAP), 256>>>(
          a, w + W_QKV + (size_t)l * 1536 * WID, bqkv + l * 1536, nullptr, qkv,
          1536, WID, nbn, nt); }
    attn_kernel<<<dim3(NFR * 2, NH, NB), 256>>>(qkv, o);
    copyv_kernel<<<(NB * NFR * 18 * WID + 255) / 256, 256>>>();
    { int nbn = WID / 128, nt = MT * nbn;
      gemm_tc<3><<<mini(nt, GEMM_GRID_CAP), 256>>>(
          o, w + W_OUT + (size_t)l * WID * WID, bout + l * WID, h, h,
          WID, WID, nbn, nt); }
    ln_kernel<<<MROWS, 256>>>(h, ln2s + l * WID, ln2b + l * WID, a);
    { int nbn = 2048 / 128, nt = MT * nbn;
      gemm_tc<2><<<mini(nt, GEMM_GRID_CAP), 256>>>(
          a, w + W_FC + (size_t)l * 2048 * WID, bfc + l * 2048, nullptr, mlp,
          2048, WID, nbn, nt); }
    { int nbn = WID / 128, nt = MT * nbn;
      gemm_tc<3><<<mini(nt, GEMM_GRID_CAP), 256>>>(
          mlp, w + W_PROJ + (size_t)l * WID * 2048, bproj + l * WID, h, h,
          WID, 2048, nbn, nt); }
  }

  gather_kernel<<<(MHEAD * WID + 255) / 256, 256>>>();
  { int nbn = 1024 / 128, nt = HT * nbn;
    gemm_tc<0><<<mini(nt, GEMM_GRID_CAP), 256>>>(
        hf, w + W_HEAD, nullptr, nullptr, out, 1024, WID, nbn, nt); }
}

// round 12
// speedup vs baseline: 1.4581x; 1.4581x over previous
#include <cuda_runtime.h>
#include <cuda_fp16.h>
#include <stdint.h>
#include <math.h>

// ---------------- problem constants ----------------
constexpr int WID    = 512;
constexpr int SEQL   = 1752;
constexpr int BLK    = 146;   // 128 frame + delim + 16 dyn + delim
constexpr int NFR    = 12;    // N frames (13-1)
constexpr int NB     = 4;     // batch
constexpr int NH     = 8;     // heads
constexpr int NLAYER = 6;
constexpr int MROWS  = NB * SEQL;        // 7008
constexpr int MPAD   = 7040;             // padded to /128
constexpr int MHEAD  = NB * NFR * 128;   // 6144 logit rows
constexpr int GEMM_GRID_CAP = 296;

// ---------------- scratch (device globals; no cudaMalloc allowed) ----------------
__device__ float  g_h  [(size_t)MPAD * WID];
__device__ __half g_a  [(size_t)MPAD * WID];
__device__ float  g_qkv[(size_t)MPAD * 3 * WID];
__device__ __half g_o  [(size_t)MPAD * WID];
__device__ __half g_mlp[(size_t)MPAD * 4 * WID];
__device__ __half g_hf [(size_t)MHEAD * WID];
// fp16 pre-converted weights: qkv | out | fc | proj | head
constexpr size_t W_QKV  = 0;
constexpr size_t W_OUT  = W_QKV + (size_t)NLAYER * 1536 * 512;
constexpr size_t W_FC   = W_OUT + (size_t)NLAYER * 512 * 512;
constexpr size_t W_PROJ = W_FC  + (size_t)NLAYER * 2048 * 512;
constexpr size_t W_HEAD = W_PROJ + (size_t)NLAYER * 512 * 2048;
constexpr size_t W_TOT  = W_HEAD + (size_t)1024 * 512;
__device__ __half g_w[W_TOT];

// ---------------- helpers ----------------
__device__ __forceinline__ uint32_t smem_u32(const void* p) {
  return (uint32_t)__cvta_generic_to_shared(p);
}

__device__ __forceinline__ void mma_f16(float* d, const uint32_t* a, const uint32_t* b) {
  asm volatile(
      "mma.sync.aligned.m16n8k16.row.col.f32.f16.f16.f32 "
      "{%0,%1,%2,%3}, {%4,%5,%6,%7}, {%8,%9}, {%0,%1,%2,%3};"
      : "+f"(d[0]), "+f"(d[1]), "+f"(d[2]), "+f"(d[3])
      : "r"(a[0]), "r"(a[1]), "r"(a[2]), "r"(a[3]), "r"(b[0]), "r"(b[1]));
}

__device__ __forceinline__ void cp_async16(uint32_t smem_dst, const void* gsrc) {
  asm volatile("cp.async.ca.shared.global [%0], [%1], 16;" :: "r"(smem_dst), "l"(gsrc));
}

// ---------------- weight fp16 pre-conversion ----------------
__global__ void round_w_kernel(const float* __restrict__ src, __half* __restrict__ dst, int n4) {
  int i = blockIdx.x * 256 + threadIdx.x;
  if (i >= n4) return;
  float4 v = ((const float4*)src)[i];
  ((__half2*)dst)[i * 2 + 0] = __floats2half2_rn(v.x, v.y);
  ((__half2*)dst)[i * 2 + 1] = __floats2half2_rn(v.z, v.w);
}

// ---------------- build h = concat(x, delim, f, delim) + pos_emb ----------------
__global__ void build_h_kernel(const float* __restrict__ x, const float* __restrict__ f,
                               const float* __restrict__ delim) {
  __shared__ float rden[256];
  int tid = threadIdx.x;
  rden[tid] = (float)(1.0 / pow(10000.0, (double)tid / 256.0));
  __syncthreads();
  int row = blockIdx.x;
  float* hr = g_h + (size_t)row * WID;
  if (row >= MROWS) { hr[tid] = 0.f; hr[tid + 256] = 0.f; return; }
  int b = row / SEQL, s = row % SEQL;
  int fi = s / BLK, r = s - fi * BLK;
  const float* src;
  if (r < 128)                    src = x + (size_t)((b * NFR + fi) * 128 + r) * WID;
  else if (r == 128 || r == 145)  src = delim;
  else                            src = f + (size_t)(b * NFR * 16 + fi * 16 + (r - 129)) * WID;
#pragma unroll
  for (int c = tid; c < WID; c += 256) {
    float ang = (float)s * rden[c >> 1];
    float p = (c & 1) ? cosf(ang) : sinf(ang);
    hr[c] = src[c] + p;
  }
}

// ---------------- LayerNorm: one block per row; output fp16 ----------------
__global__ void ln_kernel(const float* __restrict__ X, const float* __restrict__ sc,
                          const float* __restrict__ bi, __half* __restrict__ Y) {
  int row = blockIdx.x;
  const float* xr = X + (size_t)row * WID;
  int tid = threadIdx.x;
  float v0 = xr[tid], v1 = xr[tid + 256];
  float s = v0 + v1, q = v0 * v0 + v1 * v1;
#pragma unroll
  for (int o = 16; o; o >>= 1) {
    s += __shfl_xor_sync(0xffffffffu, s, o);
    q += __shfl_xor_sync(0xffffffffu, q, o);
  }
  __shared__ float ss[8], sq[8];
  if ((tid & 31) == 0) { ss[tid >> 5] = s; sq[tid >> 5] = q; }
  __syncthreads();
  float ts = 0.f, tq = 0.f;
#pragma unroll
  for (int k = 0; k < 8; k++) { ts += ss[k]; tq += sq[k]; }
  float mu = ts * (1.f / WID);
  float var = tq * (1.f / WID) - mu * mu;
  float rstd = rsqrtf(var + 1e-5f);
  __half* yr = Y + (size_t)row * WID;
  yr[tid]       = __float2half_rn((v0 - mu) * rstd * sc[tid]       + bi[tid]);
  yr[tid + 256] = __float2half_rn((v1 - mu) * rstd * sc[tid + 256] + bi[tid + 256]);
}

// ---------------- fp16 tensor-core GEMM (NT): C[m,n] = sum_k A[m,k]*B[n,k] ----------------
// 128x128 tile, persistent; 8 warps (2m x 4n), warp 64x32 via m16n8k16 f16 MMA.
// 4-stage cp.async ring (K chunks of 32 halves); smem [m][k] stride 40 halves
// (bank = 20*row + l4 + 8*ks covers all 32 -> conflict-free fragment LDS).
// EPI: 0 none, 1 +bias, 2 +bias->gelu (half out), 3 +bias+residual
template <int EPI, typename CT>
__global__ __launch_bounds__(256, 2) void gemm_hc(
    const __half* __restrict__ A, const __half* __restrict__ Bw,
    const float* __restrict__ bias, const float* __restrict__ Res,
    CT* __restrict__ C, int N, int K, int nBN, int nTiles) {
  extern __shared__ __align__(16) __half sm[];
  __half* As = sm;                    // [4][128][40]
  __half* Bs = sm + 4 * 128 * 40;
  const int tid = threadIdx.x;
  const int lane = tid & 31, wid = tid >> 5;
  const int wm = wid & 1, wn = wid >> 1;
  const int l4 = lane & 3, l28 = lane >> 2;
  const int nT = K >> 5;  // 32-half K chunks (>=16 for all shapes)

  for (int tile = blockIdx.x; tile < nTiles; tile += gridDim.x) {
    const int bm = (tile / nBN) * 128;
    const int bn = (tile % nBN) * 128;

    float acc[4][4][4];
#pragma unroll
    for (int i = 0; i < 4; i++)
#pragma unroll
      for (int j = 0; j < 4; j++)
#pragma unroll
        for (int r = 0; r < 4; r++) acc[i][j][r] = 0.f;

    auto issue = [&](int s) {
      const int buf = s & 3;
      const int kc = s << 5;
#pragma unroll
      for (int i2 = 0; i2 < 2; i2++) {
        int idx = i2 * 256 + tid;
        int row = idx >> 2, ch = idx & 3;      // 128 rows x 4 16B-chunks
        uint32_t off = (uint32_t)(buf * 5120 + row * 40 + ch * 8);
        cp_async16(smem_u32(As + off), A + (size_t)(bm + row) * K + kc + ch * 8);
        cp_async16(smem_u32(Bs + off), Bw + (size_t)(bn + row) * K + kc + ch * 8);
      }
      asm volatile("cp.async.commit_group;" ::: "memory");
    };

    issue(0); issue(1); issue(2);

    for (int it = 0; it < nT; it++) {
      asm volatile("cp.async.wait_group 2;" ::: "memory");  // stage it resident
      __syncthreads();
      if (it + 3 < nT) issue(it + 3);
      else asm volatile("cp.async.commit_group;" ::: "memory");  // lockstep groups
      const __half* Ab = As + (it & 3) * 5120;
      const __half* Bb = Bs + (it & 3) * 5120;
#pragma unroll
      for (int ks = 0; ks < 2; ks++) {  // two k16 steps per 32-half chunk
        uint32_t af[4][4], bf[4][2];
#pragma unroll
        for (int mi = 0; mi < 4; mi++) {
          const __half* pa = Ab + (wm * 64 + mi * 16 + l28) * 40 + ks * 16 + 2 * l4;
          af[mi][0] = *(const uint32_t*)pa;
          af[mi][1] = *(const uint32_t*)(pa + 8 * 40);
          af[mi][2] = *(const uint32_t*)(pa + 8);
          af[mi][3] = *(const uint32_t*)(pa + 8 * 40 + 8);
        }
#pragma unroll
        for (int nj = 0; nj < 4; nj++) {
          const __half* pb = Bb + (wn * 32 + nj * 8 + l28) * 40 + ks * 16 + 2 * l4;
          bf[nj][0] = *(const uint32_t*)pb;
          bf[nj][1] = *(const uint32_t*)(pb + 8);
        }
#pragma unroll
        for (int mi = 0; mi < 4; mi++)
#pragma unroll
          for (int nj = 0; nj < 4; nj++) mma_f16(acc[mi][nj], af[mi], bf[nj]);
      }
    }

    // epilogue: c0,c1 at (row, col..col+1), c2,c3 at (row+8, ...)
#pragma unroll
    for (int mi = 0; mi < 4; mi++) {
#pragma unroll
      for (int half = 0; half < 2; half++) {
        int row = bm + wm * 64 + mi * 16 + l28 + half * 8;
        CT* crow = C + (size_t)row * N + bn + wn * 32;
        const float* rrow = (EPI == 3) ? (Res + (size_t)row * N + bn + wn * 32) : nullptr;
#pragma unroll
        for (int nj = 0; nj < 4; nj++) {
          int col = nj * 8 + 2 * l4;
          float v0 = acc[mi][nj][half * 2 + 0];
          float v1 = acc[mi][nj][half * 2 + 1];
          if (EPI >= 1) {
            v0 += bias[bn + wn * 32 + col];
            v1 += bias[bn + wn * 32 + col + 1];
          }
          if (EPI == 2) {
            v0 = 0.5f * v0 * (1.f + erff(v0 * 0.70710678118654752f));
            v1 = 0.5f * v1 * (1.f + erff(v1 * 0.70710678118654752f));
          }
          if (EPI == 3) { v0 += rrow[col]; v1 += rrow[col + 1]; }
          if constexpr (sizeof(CT) == 2) {
            *(__half2*)(crow + col) = __floats2half2_rn(v0, v1);
          } else {
            *(float2*)(crow + col) = make_float2(v0, v1);
          }
        }
      }
    }
    __syncthreads();  // stage buffers free before next tile's issues
  }
}

constexpr int GEMM_SMEM = 4 * 128 * 40 * 2 * 2;  // 81920 bytes

// ---------------- structured attention (fp32 math; fp16 output) ----------------
__global__ __launch_bounds__(256) void attn_kernel(const float* __restrict__ qkv,
                                                   __half* __restrict__ O) {
  const int fi = blockIdx.x >> 1, qt = blockIdx.x & 1;
  const int h = blockIdx.y, b = blockIdx.z;
  const int fs = fi * BLK;
  const int q0 = fs + qt * 64;
  const int nE = (fi > 0) ? (1 + 17 * (fi + 1)) : 17;
  const int nK = 128 + nE;
  const float* base = qkv + (size_t)b * SEQL * 1536;

  __shared__ __align__(16) float Qs[64][68];
  __shared__ __align__(16) float Ks[64][68];
  __shared__ __align__(16) float Vs[64][68];
  __shared__ __align__(16) float Ps[64][68];

  const int tid = threadIdx.x;
  {
    int qr = tid >> 2;
    int c4 = tid & 3;
    const float* qrow = base + (size_t)(q0 + qr) * 1536 + h * 64;
#pragma unroll
    for (int j = 0; j < 4; j++) {
      int d = c4 * 16 + j * 4;
      float4 v = *(const float4*)(qrow + d);
      Qs[d + 0][qr] = v.x * 0.125f; Qs[d + 1][qr] = v.y * 0.125f;
      Qs[d + 2][qr] = v.z * 0.125f; Qs[d + 3][qr] = v.w * 0.125f;
    }
  }

  const int tx = tid & 15, ty = tid >> 4;
  float Oa[4][4];
  float m_run[4], l_run[4];
#pragma unroll
  for (int i = 0; i < 4; i++) {
    m_run[i] = -1e30f; l_run[i] = 0.f;
#pragma unroll
    for (int j = 0; j < 4; j++) Oa[i][j] = 0.f;
  }

  const int nCh = (nK + 63) / 64;
  for (int ch = 0; ch < nCh; ch++) {
    const int kb = ch * 64;
    __syncthreads();
    {
      int kr = tid >> 2;
      int c4 = tid & 3;
      int t = kb + kr;
      int pos;
      if (t >= nK) pos = fs;
      else if (t < 128) pos = fs + t;
      else {
        int e = t - 128;
        if (fi > 0) {
          if (e == 0) pos = fs - 1;
          else { int e2 = e - 1; pos = (e2 / 17) * BLK + 128 + (e2 % 17); }
        } else pos = 128 + e;
      }
      const float* krow = base + (size_t)pos * 1536 + 512 + h * 64;
      const float* vrow = base + (size_t)pos * 1536 + 1024 + h * 64;
      const int kc = kr ^ (c4 << 2);
#pragma unroll
      for (int j = 0; j < 4; j++) {
        int d = c4 * 16 + j * 4;
        float4 kv = *(const float4*)(krow + d);
        Ks[d + 0][kc] = kv.x; Ks[d + 1][kc] = kv.y;
        Ks[d + 2][kc] = kv.z; Ks[d + 3][kc] = kv.w;
        float4 vv = *(const float4*)(vrow + d);
        *(float4*)(&Vs[kr][d]) = vv;
      }
    }
    __syncthreads();

    float s[4][4];
#pragma unroll
    for (int i = 0; i < 4; i++)
#pragma unroll
      for (int j = 0; j < 4; j++) s[i][j] = 0.f;
#pragma unroll
    for (int d = 0; d < 64; d++) {
      float4 qv = *(const float4*)(&Qs[d][ty * 4]);
      float4 kv = *(const float4*)(&Ks[d][(tx * 4) ^ ((d >> 4) << 2)]);
      float qa[4] = {qv.x, qv.y, qv.z, qv.w};
      float ka[4] = {kv.x, kv.y, kv.z, kv.w};
#pragma unroll
      for (int i = 0; i < 4; i++)
#pragma unroll
        for (int j = 0; j < 4; j++) s[i][j] = fmaf(qa[i], ka[j], s[i][j]);
    }
#pragma unroll
    for (int j = 0; j < 4; j++)
      if (kb + tx * 4 + j >= nK)
#pragma unroll
        for (int i = 0; i < 4; i++) s[i][j] = -1e30f;

#pragma unroll
    for (int i = 0; i < 4; i++) {
      float mx = fmaxf(fmaxf(s[i][0], s[i][1]), fmaxf(s[i][2], s[i][3]));
#pragma unroll
      for (int o = 1; o < 16; o <<= 1) mx = fmaxf(mx, __shfl_xor_sync(0xffffffffu, mx, o));
      float mn = fmaxf(m_run[i], mx);
      float al = expf(m_run[i] - mn);
      float ls = 0.f;
#pragma unroll
      for (int j = 0; j < 4; j++) {
        float p = expf(s[i][j] - mn);
        s[i][j] = p;
        ls += p;
      }
#pragma unroll
      for (int o = 1; o < 16; o <<= 1) ls += __shfl_xor_sync(0xffffffffu, ls, o);
      m_run[i] = mn;
      l_run[i] = l_run[i] * al + ls;
#pragma unroll
      for (int j = 0; j < 4; j++) Oa[i][j] *= al;
    }
#pragma unroll
    for (int i = 0; i < 4; i++)
      *(float4*)(&Ps[ty * 4 + i][tx * 4]) = make_float4(s[i][0], s[i][1], s[i][2], s[i][3]);
    __syncwarp();

#pragma unroll
    for (int kq = 0; kq < 16; kq++) {
      float4 vr[4];
#pragma unroll
      for (int t2 = 0; t2 < 4; t2++) vr[t2] = *(const float4*)(&Vs[kq * 4 + t2][tx * 4]);
#pragma unroll
      for (int i = 0; i < 4; i++) {
        float4 pr = *(const float4*)(&Ps[ty * 4 + i][kq * 4]);
        Oa[i][0] = fmaf(pr.x, vr[0].x, fmaf(pr.y, vr[1].x, fmaf(pr.z, vr[2].x, fmaf(pr.w, vr[3].x, Oa[i][0]))));
        Oa[i][1] = fmaf(pr.x, vr[0].y, fmaf(pr.y, vr[1].y, fmaf(pr.z, vr[2].y, fmaf(pr.w, vr[3].y, Oa[i][1]))));
        Oa[i][2] = fmaf(pr.x, vr[0].z, fmaf(pr.y, vr[1].z, fmaf(pr.z, vr[2].z, fmaf(pr.w, vr[3].z, Oa[i][2]))));
        Oa[i][3] = fmaf(pr.x, vr[0].w, fmaf(pr.y, vr[1].w, fmaf(pr.z, vr[2].w, fmaf(pr.w, vr[3].w, Oa[i][3]))));
      }
    }
  }

#pragma unroll
  for (int i = 0; i < 4; i++) {
    int q = ty * 4 + i;
    float inv = 1.f / l_run[i];
    __half* orow = O + (size_t)(b * SEQL + q0 + q) * WID + h * 64 + tx * 4;
    ((__half2*)orow)[0] = __floats2half2_rn(Oa[i][0] * inv, Oa[i][1] * inv);
    ((__half2*)orow)[1] = __floats2half2_rn(Oa[i][2] * inv, Oa[i][3] * inv);
  }
}

// ---------------- non-frame rows: attention output == V (fp16) ----------------
__global__ void copyv_kernel() {
  int idx = blockIdx.x * 256 + threadIdx.x;
  if (idx >= NB * NFR * 18 * WID) return;
  int c = idx & 511;
  int rid = idx >> 9;
  int b = rid / (NFR * 18);
  int rr = rid % (NFR * 18);
  int fi = rr / 18, r = 128 + rr % 18;
  size_t srow = (size_t)b * SEQL + fi * BLK + r;
  g_o[srow * WID + c] = __float2half_rn(g_qkv[srow * 1536 + 1024 + c]);
}

// ---------------- gather frame-token rows for the prediction head (fp16) ----------------
__global__ void gather_kernel() {
  int idx = blockIdx.x * 256 + threadIdx.x;
  if (idx >= MHEAD * WID) return;
  int c = idx & 511, rid = idx >> 9;
  int b = rid / 1536, m = rid % 1536;
  int s = (m >> 7) * BLK + (m & 127);
  g_hf[(size_t)rid * WID + c] = __float2half_rn(g_h[(size_t)(b * SEQL + s) * WID + c]);
}

// ---------------- launch ----------------
static inline int mini(int a, int b) { return a < b ? a : b; }

extern "C" void kernel_launch(void* const* d_in, const int* in_sizes, int n_in,
                              void* d_out, int out_size) {
  const float* x     = (const float*)d_in[0];
  const float* f     = (const float*)d_in[1];
  const float* delim = (const float*)d_in[2];
  const float* ln1s  = (const float*)d_in[3];
  const float* ln1b  = (const float*)d_in[4];
  const float* wqkv  = (const float*)d_in[5];
  const float* bqkv  = (const float*)d_in[6];
  const float* wout  = (const float*)d_in[7];
  const float* bout  = (const float*)d_in[8];
  const float* ln2s  = (const float*)d_in[9];
  const float* ln2b  = (const float*)d_in[10];
  const float* wfc   = (const float*)d_in[11];
  const float* bfc   = (const float*)d_in[12];
  const float* wproj = (const float*)d_in[13];
  const float* bproj = (const float*)d_in[14];
  const float* whead = (const float*)d_in[15];
  float* out = (float*)d_out;

  float *h, *qkv;
  __half *a, *o, *mlp, *hf, *w;
  cudaGetSymbolAddress((void**)&h, g_h);
  cudaGetSymbolAddress((void**)&a, g_a);
  cudaGetSymbolAddress((void**)&qkv, g_qkv);
  cudaGetSymbolAddress((void**)&o, g_o);
  cudaGetSymbolAddress((void**)&mlp, g_mlp);
  cudaGetSymbolAddress((void**)&hf, g_hf);
  cudaGetSymbolAddress((void**)&w, g_w);

  cudaFuncSetAttribute(gemm_hc<0, float>,  cudaFuncAttributeMaxDynamicSharedMemorySize, GEMM_SMEM);
  cudaFuncSetAttribute(gemm_hc<1, float>,  cudaFuncAttributeMaxDynamicSharedMemorySize, GEMM_SMEM);
  cudaFuncSetAttribute(gemm_hc<2, __half>, cudaFuncAttributeMaxDynamicSharedMemorySize, GEMM_SMEM);
  cudaFuncSetAttribute(gemm_hc<3, float>,  cudaFuncAttributeMaxDynamicSharedMemorySize, GEMM_SMEM);

  // pre-convert all weights to fp16
  {
    int n;
    n = NLAYER * 1536 * 512 / 4;
    round_w_kernel<<<(n + 255) / 256, 256>>>(wqkv, w + W_QKV, n);
    n = NLAYER * 512 * 512 / 4;
    round_w_kernel<<<(n + 255) / 256, 256>>>(wout, w + W_OUT, n);
    n = NLAYER * 2048 * 512 / 4;
    round_w_kernel<<<(n + 255) / 256, 256>>>(wfc, w + W_FC, n);
    n = NLAYER * 512 * 2048 / 4;
    round_w_kernel<<<(n + 255) / 256, 256>>>(wproj, w + W_PROJ, n);
    n = 1024 * 512 / 4;
    round_w_kernel<<<(n + 255) / 256, 256>>>(whead, w + W_HEAD, n);
  }

  build_h_kernel<<<MPAD, 256>>>(x, f, delim);

  const int MT = MPAD / 128;   // 55
  const int HT = MHEAD / 128;  // 48

  for (int l = 0; l < NLAYER; l++) {
    ln_kernel<<<MROWS, 256>>>(h, ln1s + l * WID, ln1b + l * WID, a);
    { int nbn = 1536 / 128, nt = MT * nbn;
      gemm_hc<1, float><<<mini(nt, GEMM_GRID_CAP), 256, GEMM_SMEM>>>(
          a, w + W_QKV + (size_t)l * 1536 * WID, bqkv + l * 1536, nullptr, qkv,
          1536, WID, nbn, nt); }
    attn_kernel<<<dim3(NFR * 2, NH, NB), 256>>>(qkv, o);
    copyv_kernel<<<(NB * NFR * 18 * WID + 255) / 256, 256>>>();
    { int nbn = WID / 128, nt = MT * nbn;
      gemm_hc<3, float><<<mini(nt, GEMM_GRID_CAP), 256, GEMM_SMEM>>>(
          o, w + W_OUT + (size_t)l * WID * WID, bout + l * WID, h, h,
          WID, WID, nbn, nt); }
    ln_kernel<<<MROWS, 256>>>(h, ln2s + l * WID, ln2b + l * WID, a);
    { int nbn = 2048 / 128, nt = MT * nbn;
      gemm_hc<2, __half><<<mini(nt, GEMM_GRID_CAP), 256, GEMM_SMEM>>>(
          a, w + W_FC + (size_t)l * 2048 * WID, bfc + l * 2048, nullptr, mlp,
          2048, WID, nbn, nt); }
    { int nbn = WID / 128, nt = MT * nbn;
      gemm_hc<3, float><<<mini(nt, GEMM_GRID_CAP), 256, GEMM_SMEM>>>(
          mlp, w + W_PROJ + (size_t)l * WID * 2048, bproj + l * WID, h, h,
          WID, 2048, nbn, nt); }
  }

  gather_kernel<<<(MHEAD * WID + 255) / 256, 256>>>();
  { int nbn = 1024 / 128, nt = HT * nbn;
    gemm_hc<0, float><<<mini(nt, GEMM_GRID_CAP), 256, GEMM_SMEM>>>(
        hf, w + W_HEAD, nullptr, nullptr, out, 1024, WID, nbn, nt); }
}

// round 15
// speedup vs baseline: 1.8390x; 1.2612x over previous
#include <cuda_runtime.h>
#include <cuda_fp16.h>
#include <stdint.h>
#include <math.h>

// ---------------- problem constants ----------------
constexpr int WID    = 512;
constexpr int SEQL   = 1752;
constexpr int BLK    = 146;   // 128 frame + delim + 16 dyn + delim
constexpr int NFR    = 12;    // N frames (13-1)
constexpr int NB     = 4;     // batch
constexpr int NH     = 8;     // heads
constexpr int NLAYER = 6;
constexpr int MROWS  = NB * SEQL;        // 7008
constexpr int MPAD   = 7040;             // padded to /128
constexpr int MHEAD  = NB * NFR * 128;   // 6144 logit rows
constexpr int GEMM_GRID_CAP = 296;

// ---------------- scratch (device globals; no cudaMalloc allowed) ----------------
__device__ float  g_h  [(size_t)MPAD * WID];
__device__ __half g_a  [(size_t)MPAD * WID];
__device__ __half g_qkv[(size_t)MPAD * 3 * WID];
__device__ __half g_o  [(size_t)MPAD * WID];
__device__ __half g_mlp[(size_t)MPAD * 4 * WID];
__device__ __half g_hf [(size_t)MHEAD * WID];
// fp16 pre-converted weights: qkv | out | fc | proj | head
constexpr size_t W_QKV  = 0;
constexpr size_t W_OUT  = W_QKV + (size_t)NLAYER * 1536 * 512;
constexpr size_t W_FC   = W_OUT + (size_t)NLAYER * 512 * 512;
constexpr size_t W_PROJ = W_FC  + (size_t)NLAYER * 2048 * 512;
constexpr size_t W_HEAD = W_PROJ + (size_t)NLAYER * 512 * 2048;
constexpr size_t W_TOT  = W_HEAD + (size_t)1024 * 512;
__device__ __half g_w[W_TOT];

// ---------------- helpers ----------------
__device__ __forceinline__ uint32_t smem_u32(const void* p) {
  return (uint32_t)__cvta_generic_to_shared(p);
}

__device__ __forceinline__ void mma_f16(float* d, const uint32_t* a, const uint32_t* b) {
  asm volatile(
      "mma.sync.aligned.m16n8k16.row.col.f32.f16.f16.f32 "
      "{%0,%1,%2,%3}, {%4,%5,%6,%7}, {%8,%9}, {%0,%1,%2,%3};"
      : "+f"(d[0]), "+f"(d[1]), "+f"(d[2]), "+f"(d[3])
      : "r"(a[0]), "r"(a[1]), "r"(a[2]), "r"(a[3]), "r"(b[0]), "r"(b[1]));
}

__device__ __forceinline__ void cp_async16(uint32_t smem_dst, const void* gsrc) {
  asm volatile("cp.async.ca.shared.global [%0], [%1], 16;" :: "r"(smem_dst), "l"(gsrc));
}

// ---------------- weight fp16 pre-conversion ----------------
__global__ void round_w_kernel(const float* __restrict__ src, __half* __restrict__ dst, int n4) {
  int i = blockIdx.x * 256 + threadIdx.x;
  if (i >= n4) return;
  float4 v = ((const float4*)src)[i];
  ((__half2*)dst)[i * 2 + 0] = __floats2half2_rn(v.x, v.y);
  ((__half2*)dst)[i * 2 + 1] = __floats2half2_rn(v.z, v.w);
}

// ---------------- build h = concat(x, delim, f, delim) + pos_emb ----------------
__global__ void build_h_kernel(const float* __restrict__ x, const float* __restrict__ f,
                               const float* __restrict__ delim) {
  __shared__ float rden[256];
  int tid = threadIdx.x;
  rden[tid] = (float)(1.0 / pow(10000.0, (double)tid / 256.0));
  __syncthreads();
  int row = blockIdx.x;
  float* hr = g_h + (size_t)row * WID;
  if (row >= MROWS) { hr[tid] = 0.f; hr[tid + 256] = 0.f; return; }
  int b = row / SEQL, s = row % SEQL;
  int fi = s / BLK, r = s - fi * BLK;
  const float* src;
  if (r < 128)                    src = x + (size_t)((b * NFR + fi) * 128 + r) * WID;
  else if (r == 128 || r == 145)  src = delim;
  else                            src = f + (size_t)(b * NFR * 16 + fi * 16 + (r - 129)) * WID;
#pragma unroll
  for (int c = tid; c < WID; c += 256) {
    float ang = (float)s * rden[c >> 1];
    float p = (c & 1) ? cosf(ang) : sinf(ang);
    hr[c] = src[c] + p;
  }
}

// ---------------- LayerNorm: one block per row; output fp16 ----------------
__global__ void ln_kernel(const float* __restrict__ X, const float* __restrict__ sc,
                          const float* __restrict__ bi, __half* __restrict__ Y) {
  int row = blockIdx.x;
  const float* xr = X + (size_t)row * WID;
  int tid = threadIdx.x;
  float v0 = xr[tid], v1 = xr[tid + 256];
  float s = v0 + v1, q = v0 * v0 + v1 * v1;
#pragma unroll
  for (int o = 16; o; o >>= 1) {
    s += __shfl_xor_sync(0xffffffffu, s, o);
    q += __shfl_xor_sync(0xffffffffu, q, o);
  }
  __shared__ float ss[8], sq[8];
  if ((tid & 31) == 0) { ss[tid >> 5] = s; sq[tid >> 5] = q; }
  __syncthreads();
  float ts = 0.f, tq = 0.f;
#pragma unroll
  for (int k = 0; k < 8; k++) { ts += ss[k]; tq += sq[k]; }
  float mu = ts * (1.f / WID);
  float var = tq * (1.f / WID) - mu * mu;
  float rstd = rsqrtf(var + 1e-5f);
  __half* yr = Y + (size_t)row * WID;
  yr[tid]       = __float2half_rn((v0 - mu) * rstd * sc[tid]       + bi[tid]);
  yr[tid + 256] = __float2half_rn((v1 - mu) * rstd * sc[tid + 256] + bi[tid + 256]);
}

// ---------------- fp16 tensor-core GEMM (NT), persistent tiles ----------------
template <int EPI, typename CT>
__global__ __launch_bounds__(256, 2) void gemm_hc(
    const __half* __restrict__ A, const __half* __restrict__ Bw,
    const float* __restrict__ bias, const float* __restrict__ Res,
    CT* __restrict__ C, int N, int K, int nBN, int nTiles) {
  extern __shared__ __align__(16) __half sm[];
  __half* As = sm;                    // [4][128][40]
  __half* Bs = sm + 4 * 128 * 40;
  const int tid = threadIdx.x;
  const int lane = tid & 31, wid = tid >> 5;
  const int wm = wid & 1, wn = wid >> 1;
  const int l4 = lane & 3, l28 = lane >> 2;
  const int nT = K >> 5;

  for (int tile = blockIdx.x; tile < nTiles; tile += gridDim.x) {
    const int bm = (tile / nBN) * 128;
    const int bn = (tile % nBN) * 128;

    float acc[4][4][4];
#pragma unroll
    for (int i = 0; i < 4; i++)
#pragma unroll
      for (int j = 0; j < 4; j++)
#pragma unroll
        for (int r = 0; r < 4; r++) acc[i][j][r] = 0.f;

    auto issue = [&](int s) {
      const int buf = s & 3;
      const int kc = s << 5;
#pragma unroll
      for (int i2 = 0; i2 < 2; i2++) {
        int idx = i2 * 256 + tid;
        int row = idx >> 2, ch = idx & 3;
        uint32_t off = (uint32_t)(buf * 5120 + row * 40 + ch * 8);
        cp_async16(smem_u32(As + off), A + (size_t)(bm + row) * K + kc + ch * 8);
        cp_async16(smem_u32(Bs + off), Bw + (size_t)(bn + row) * K + kc + ch * 8);
      }
      asm volatile("cp.async.commit_group;" ::: "memory");
    };

    issue(0); issue(1); issue(2);

    for (int it = 0; it < nT; it++) {
      asm volatile("cp.async.wait_group 2;" ::: "memory");
      __syncthreads();
      if (it + 3 < nT) issue(it + 3);
      else asm volatile("cp.async.commit_group;" ::: "memory");
      const __half* Ab = As + (it & 3) * 5120;
      const __half* Bb = Bs + (it & 3) * 5120;
#pragma unroll
      for (int ks = 0; ks < 2; ks++) {
        uint32_t af[4][4], bf[4][2];
#pragma unroll
        for (int mi = 0; mi < 4; mi++) {
          const __half* pa = Ab + (wm * 64 + mi * 16 + l28) * 40 + ks * 16 + 2 * l4;
          af[mi][0] = *(const uint32_t*)pa;
          af[mi][1] = *(const uint32_t*)(pa + 8 * 40);
          af[mi][2] = *(const uint32_t*)(pa + 8);
          af[mi][3] = *(const uint32_t*)(pa + 8 * 40 + 8);
        }
#pragma unroll
        for (int nj = 0; nj < 4; nj++) {
          const __half* pb = Bb + (wn * 32 + nj * 8 + l28) * 40 + ks * 16 + 2 * l4;
          bf[nj][0] = *(const uint32_t*)pb;
          bf[nj][1] = *(const uint32_t*)(pb + 8);
        }
#pragma unroll
        for (int mi = 0; mi < 4; mi++)
#pragma unroll
          for (int nj = 0; nj < 4; nj++) mma_f16(acc[mi][nj], af[mi], bf[nj]);
      }
    }

#pragma unroll
    for (int mi = 0; mi < 4; mi++) {
#pragma unroll
      for (int half = 0; half < 2; half++) {
        int row = bm + wm * 64 + mi * 16 + l28 + half * 8;
        CT* crow = C + (size_t)row * N + bn + wn * 32;
        const float* rrow = (EPI == 3) ? (Res + (size_t)row * N + bn + wn * 32) : nullptr;
#pragma unroll
        for (int nj = 0; nj < 4; nj++) {
          int col = nj * 8 + 2 * l4;
          float v0 = acc[mi][nj][half * 2 + 0];
          float v1 = acc[mi][nj][half * 2 + 1];
          if (EPI >= 1) {
            v0 += bias[bn + wn * 32 + col];
            v1 += bias[bn + wn * 32 + col + 1];
          }
          if (EPI == 2) {
            v0 = 0.5f * v0 * (1.f + erff(v0 * 0.70710678118654752f));
            v1 = 0.5f * v1 * (1.f + erff(v1 * 0.70710678118654752f));
          }
          if (EPI == 3) { v0 += rrow[col]; v1 += rrow[col + 1]; }
          if constexpr (sizeof(CT) == 2) {
            *(__half2*)(crow + col) = __floats2half2_rn(v0, v1);
          } else {
            *(float2*)(crow + col) = make_float2(v0, v1);
          }
        }
      }
    }
    __syncthreads();
  }
}

constexpr int GEMM_SMEM = 4 * 128 * 40 * 2 * 2;  // 81920 bytes

// ---------------- gathered key position for frame fi ----------------
__device__ __forceinline__ int key_pos(int fi, int fs, int nK, int t) {
  if (t >= nK) return fs;
  if (t < 128) return fs + t;
  int e = t - 128;
  if (fi > 0) {
    if (e == 0) return fs - 1;
    int e2 = e - 1;
    return (e2 / 17) * BLK + 128 + (e2 % 17);
  }
  return 128 + e;
}

// ---------------- tensor-core attention ----------------
// Block = (frame, head, batch); 8 warps, warp w owns q rows w*16..w*16+15.
// 64-key chunks: S = Q@K^T via m16n8k16 (fp32 acc), online softmax in registers,
// P fragments taken directly from S accumulators, O += P@V via m16n8k16.
__global__ __launch_bounds__(256, 2) void attn_kernel(const __half* __restrict__ qkv,
                                                      __half* __restrict__ O) {
  const int fi = blockIdx.x, h = blockIdx.y, b = blockIdx.z;
  const int fs = fi * BLK;
  const int nE = (fi > 0) ? (1 + 17 * (fi + 1)) : 17;
  const int nK = 128 + nE;
  const __half* base = qkv + (size_t)b * SEQL * 1536;

  __shared__ __align__(16) __half Qs[128 * 72];  // [q][d]
  __shared__ __align__(16) __half Ks[64 * 72];   // [key][d]
  __shared__ __align__(16) __half Vs[64 * 72];   // [d][key] (transposed)

  const int tid = threadIdx.x;
  const int lane = tid & 31, w = tid >> 5;
  const int l4 = lane & 3, l28 = lane >> 2;

  // load Q tile (128 q x 64 d fp16) via cp.async
#pragma unroll
  for (int i = 0; i < 4; i++) {
    int idx = i * 256 + tid;
    int row = idx >> 3, ch = idx & 7;
    cp_async16(smem_u32(Qs + row * 72 + ch * 8),
               base + (size_t)(fs + row) * 1536 + h * 64 + ch * 8);
  }
  asm volatile("cp.async.commit_group;" ::: "memory");

  float s[8][4], o[8][4];
  float m_run[2] = {-1e30f, -1e30f}, l_run[2] = {0.f, 0.f};
#pragma unroll
  for (int n = 0; n < 8; n++)
#pragma unroll
    for (int r = 0; r < 4; r++) o[n][r] = 0.f;

  const int nCh = (nK + 63) / 64;
  for (int ch = 0; ch < nCh; ch++) {
    const int kb = ch * 64;
    __syncthreads();  // previous chunk's MMAs done before overwriting K/V
    {  // K rows via cp.async
#pragma unroll
      for (int i = 0; i < 2; i++) {
        int idx = i * 256 + tid;
        int row = idx >> 3, c8 = idx & 7;
        int pos = key_pos(fi, fs, nK, kb + row);
        cp_async16(smem_u32(Ks + row * 72 + c8 * 8),
                   base + (size_t)pos * 1536 + 512 + h * 64 + c8 * 8);
      }
      asm volatile("cp.async.commit_group;" ::: "memory");
      // V transposed: thread covers key k, d range dg*16..+15
      int k = tid & 63, dg = tid >> 6;
      int pos = key_pos(fi, fs, nK, kb + k);
      const __half* vrow = base + (size_t)pos * 1536 + 1024 + h * 64 + dg * 16;
      float4 p0 = *(const float4*)(vrow);      // 8 halves
      float4 p1 = *(const float4*)(vrow + 8);
      const __half* hp0 = (const __half*)&p0;
      const __half* hp1 = (const __half*)&p1;
#pragma unroll
      for (int j = 0; j < 8; j++) {
        Vs[(dg * 16 + j) * 72 + k]     = hp0[j];
        Vs[(dg * 16 + 8 + j) * 72 + k] = hp1[j];
      }
    }
    asm volatile("cp.async.wait_group 0;" ::: "memory");
    __syncthreads();

    // S = Q @ K^T
#pragma unroll
    for (int n = 0; n < 8; n++)
#pragma unroll
      for (int r = 0; r < 4; r++) s[n][r] = 0.f;
#pragma unroll
    for (int kt = 0; kt < 4; kt++) {
      uint32_t a[4];
      const __half* pa = Qs + (w * 16 + l28) * 72 + kt * 16 + 2 * l4;
      a[0] = *(const uint32_t*)pa;
      a[1] = *(const uint32_t*)(pa + 8 * 72);
      a[2] = *(const uint32_t*)(pa + 8);
      a[3] = *(const uint32_t*)(pa + 8 * 72 + 8);
#pragma unroll
      for (int n = 0; n < 8; n++) {
        uint32_t bfr[2];
        const __half* pb = Ks + (n * 8 + l28) * 72 + kt * 16 + 2 * l4;
        bfr[0] = *(const uint32_t*)pb;
        bfr[1] = *(const uint32_t*)(pb + 8);
        mma_f16(s[n], a, bfr);
      }
    }
    // scale + mask
#pragma unroll
    for (int n = 0; n < 8; n++) {
      int col = kb + n * 8 + 2 * l4;
      bool v0 = (col < nK), v1 = (col + 1 < nK);
      s[n][0] = v0 ? s[n][0] * 0.125f : -1e30f;
      s[n][1] = v1 ? s[n][1] * 0.125f : -1e30f;
      s[n][2] = v0 ? s[n][2] * 0.125f : -1e30f;
      s[n][3] = v1 ? s[n][3] * 0.125f : -1e30f;
    }
    // online softmax per row-half (rows l28 -> regs 0,1; l28+8 -> regs 2,3)
#pragma unroll
    for (int hr = 0; hr < 2; hr++) {
      const int r0 = hr * 2, r1 = hr * 2 + 1;
      float mx = -1e30f;
#pragma unroll
      for (int n = 0; n < 8; n++) mx = fmaxf(mx, fmaxf(s[n][r0], s[n][r1]));
      mx = fmaxf(mx, __shfl_xor_sync(0xffffffffu, mx, 1));
      mx = fmaxf(mx, __shfl_xor_sync(0xffffffffu, mx, 2));
      float mn = fmaxf(m_run[hr], mx);
      float al = __expf(m_run[hr] - mn);
      float ls = 0.f;
#pragma unroll
      for (int n = 0; n < 8; n++) {
        float p0 = __expf(s[n][r0] - mn);
        float p1 = __expf(s[n][r1] - mn);
        s[n][r0] = p0; s[n][r1] = p1;
        ls += p0 + p1;
      }
      ls += __shfl_xor_sync(0xffffffffu, ls, 1);
      ls += __shfl_xor_sync(0xffffffffu, ls, 2);
      m_run[hr] = mn;
      l_run[hr] = l_run[hr] * al + ls;
#pragma unroll
      for (int n = 0; n < 8; n++) { o[n][r0] *= al; o[n][r1] *= al; }
    }
    // O += P @ V (P fragments from S accumulators)
#pragma unroll
    for (int kt = 0; kt < 4; kt++) {
      uint32_t a[4];
      __half2 h0 = __floats2half2_rn(s[2 * kt][0], s[2 * kt][1]);
      __half2 h1 = __floats2half2_rn(s[2 * kt][2], s[2 * kt][3]);
      __half2 h2 = __floats2half2_rn(s[2 * kt + 1][0], s[2 * kt + 1][1]);
      __half2 h3 = __floats2half2_rn(s[2 * kt + 1][2], s[2 * kt + 1][3]);
      a[0] = *(uint32_t*)&h0; a[1] = *(uint32_t*)&h1;
      a[2] = *(uint32_t*)&h2; a[3] = *(uint32_t*)&h3;
#pragma unroll
      for (int n = 0; n < 8; n++) {
        uint32_t bfr[2];
        const __half* pb = Vs + (n * 8 + l28) * 72 + kt * 16 + 2 * l4;
        bfr[0] = *(const uint32_t*)pb;
        bfr[1] = *(const uint32_t*)(pb + 8);
        mma_f16(o[n], a, bfr);
      }
    }
  }

  // write O (fp16), rows w*16+l28 and +8
  float inv0 = 1.f / l_run[0], inv1 = 1.f / l_run[1];
#pragma unroll
  for (int n = 0; n < 8; n++) {
    int q = fs + w * 16 + l28;
    int d = h * 64 + n * 8 + 2 * l4;
    __half* o0 = O + (size_t)(b * SEQL + q) * WID + d;
    __half* o1 = O + (size_t)(b * SEQL + q + 8) * WID + d;
    *(__half2*)o0 = __floats2half2_rn(o[n][0] * inv0, o[n][1] * inv0);
    *(__half2*)o1 = __floats2half2_rn(o[n][2] * inv1, o[n][3] * inv1);
  }
}

// ---------------- non-frame rows: attention output == V (fp16 copy) ----------------
__global__ void copyv_kernel() {
  int idx = blockIdx.x * 256 + threadIdx.x;
  if (idx >= NB * NFR * 18 * WID) return;
  int c = idx & 511;
  int rid = idx >> 9;
  int b = rid / (NFR * 18);
  int rr = rid % (NFR * 18);
  int fi = rr / 18, r = 128 + rr % 18;
  size_t srow = (size_t)b * SEQL + fi * BLK + r;
  g_o[srow * WID + c] = g_qkv[srow * 1536 + 1024 + c];
}

// ---------------- gather frame-token rows for the prediction head (fp16) ----------------
__global__ void gather_kernel() {
  int idx = blockIdx.x * 256 + threadIdx.x;
  if (idx >= MHEAD * WID) return;
  int c = idx & 511, rid = idx >> 9;
  int b = rid / 1536, m = rid % 1536;
  int s = (m >> 7) * BLK + (m & 127);
  g_hf[(size_t)rid * WID + c] = __float2half_rn(g_h[(size_t)(b * SEQL + s) * WID + c]);
}

// ---------------- launch ----------------
static inline int mini(int a, int b) { return a < b ? a : b; }

extern "C" void kernel_launch(void* const* d_in, const int* in_sizes, int n_in,
                              void* d_out, int out_size) {
  const float* x     = (const float*)d_in[0];
  const float* f     = (const float*)d_in[1];
  const float* delim = (const float*)d_in[2];
  const float* ln1s  = (const float*)d_in[3];
  const float* ln1b  = (const float*)d_in[4];
  const float* wqkv  = (const float*)d_in[5];
  const float* bqkv  = (const float*)d_in[6];
  const float* wout  = (const float*)d_in[7];
  const float* bout  = (const float*)d_in[8];
  const float* ln2s  = (const float*)d_in[9];
  const float* ln2b  = (const float*)d_in[10];
  const float* wfc   = (const float*)d_in[11];
  const float* bfc   = (const float*)d_in[12];
  const float* wproj = (const float*)d_in[13];
  const float* bproj = (const float*)d_in[14];
  const float* whead = (const float*)d_in[15];
  float* out = (float*)d_out;

  float *h;
  __half *a, *qkv, *o, *mlp, *hf, *w;
  cudaGetSymbolAddress((void**)&h, g_h);
  cudaGetSymbolAddress((void**)&a, g_a);
  cudaGetSymbolAddress((void**)&qkv, g_qkv);
  cudaGetSymbolAddress((void**)&o, g_o);
  cudaGetSymbolAddress((void**)&mlp, g_mlp);
  cudaGetSymbolAddress((void**)&hf, g_hf);
  cudaGetSymbolAddress((void**)&w, g_w);

  cudaFuncSetAttribute(gemm_hc<0, float>,  cudaFuncAttributeMaxDynamicSharedMemorySize, GEMM_SMEM);
  cudaFuncSetAttribute(gemm_hc<1, __half>, cudaFuncAttributeMaxDynamicSharedMemorySize, GEMM_SMEM);
  cudaFuncSetAttribute(gemm_hc<2, __half>, cudaFuncAttributeMaxDynamicSharedMemorySize, GEMM_SMEM);
  cudaFuncSetAttribute(gemm_hc<3, float>,  cudaFuncAttributeMaxDynamicSharedMemorySize, GEMM_SMEM);

  // pre-convert all weights to fp16
  {
    int n;
    n = NLAYER * 1536 * 512 / 4;
    round_w_kernel<<<(n + 255) / 256, 256>>>(wqkv, w + W_QKV, n);
    n = NLAYER * 512 * 512 / 4;
    round_w_kernel<<<(n + 255) / 256, 256>>>(wout, w + W_OUT, n);
    n = NLAYER * 2048 * 512 / 4;
    round_w_kernel<<<(n + 255) / 256, 256>>>(wfc, w + W_FC, n);
    n = NLAYER * 512 * 2048 / 4;
    round_w_kernel<<<(n + 255) / 256, 256>>>(wproj, w + W_PROJ, n);
    n = 1024 * 512 / 4;
    round_w_kernel<<<(n + 255) / 256, 256>>>(whead, w + W_HEAD, n);
  }

  build_h_kernel<<<MPAD, 256>>>(x, f, delim);

  const int MT = MPAD / 128;   // 55
  const int HT = MHEAD / 128;  // 48

  for (int l = 0; l < NLAYER; l++) {
    ln_kernel<<<MROWS, 256>>>(h, ln1s + l * WID, ln1b + l * WID, a);
    { int nbn = 1536 / 128, nt = MT * nbn;
      gemm_hc<1, __half><<<mini(nt, GEMM_GRID_CAP), 256, GEMM_SMEM>>>(
          a, w + W_QKV + (size_t)l * 1536 * WID, bqkv + l * 1536, nullptr, qkv,
          1536, WID, nbn, nt); }
    attn_kernel<<<dim3(NFR, NH, NB), 256>>>(qkv, o);
    copyv_kernel<<<(NB * NFR * 18 * WID + 255) / 256, 256>>>();
    { int nbn = WID / 128, nt = MT * nbn;
      gemm_hc<3, float><<<mini(nt, GEMM_GRID_CAP), 256, GEMM_SMEM>>>(
          o, w + W_OUT + (size_t)l * WID * WID, bout + l * WID, h, h,
          WID, WID, nbn, nt); }
    ln_kernel<<<MROWS, 256>>>(h, ln2s + l * WID, ln2b + l * WID, a);
    { int nbn = 2048 / 128, nt = MT * nbn;
      gemm_hc<2, __half><<<mini(nt, GEMM_GRID_CAP), 256, GEMM_SMEM>>>(
          a, w + W_FC + (size_t)l * 2048 * WID, bfc + l * 2048, nullptr, mlp,
          2048, WID, nbn, nt); }
    { int nbn = WID / 128, nt = MT * nbn;
      gemm_hc<3, float><<<mini(nt, GEMM_GRID_CAP), 256, GEMM_SMEM>>>(
          mlp, w + W_PROJ + (size_t)l * WID * 2048, bproj + l * WID, h, h,
          WID, 2048, nbn, nt); }
  }

  gather_kernel<<<(MHEAD * WID + 255) / 256, 256>>>();
  { int nbn = 1024 / 128, nt = HT * nbn;
    gemm_hc<0, float><<<mini(nt, GEMM_GRID_CAP), 256, GEMM_SMEM>>>(
        hf, w + W_HEAD, nullptr, nullptr, out, 1024, WID, nbn, nt); }
}